// round 9
// baseline (speedup 1.0000x reference)
#include <cuda_runtime.h>
#include <cuda_bf16.h>

#define TH 256
#define MT 32
#define XAP 360   // XA row pitch (K up to 360)
#define XBP 260   // XB row pitch
#define KTP 12    // W tile k-pitch: 8 k + 4 pad (stride 3 float4 -> conflict-free)

// ---------------- device globals (no allocs allowed) ----------------
__device__ float g_scores[8 * 4096];
__device__ float g_probs[8 * 4096];
__device__ float g_cWt[256 * 360];    // combine W transposed [c][k], k padded to 360
__device__ float g_w1t[256 * 256];
__device__ float g_w2at[256 * 256];
__device__ float g_w2bt[256 * 256];
__device__ float g_vft[8 * 256 * 48]; // vf transposed per batch [b][g][a]

typedef unsigned long long ull;

__device__ __forceinline__ ull pk2(float a, float b) {
    ull r;
    asm("mov.b64 %0, {%1,%2};" : "=l"(r) : "f"(a), "f"(b));
    return r;
}
__device__ __forceinline__ void upk2(ull v, float& a, float& b) {
    asm("mov.b64 {%0,%1}, %2;" : "=f"(a), "=f"(b) : "l"(v));
}
__device__ __forceinline__ ull fma2(ull a, ull b, ull c) {
    ull d;
    asm("fma.rn.f32x2 %0, %1, %2, %3;" : "=l"(d) : "l"(a), "l"(b), "l"(c));
    return d;
}

// ---------------- row-wise instance norm over 256 dims, row-major X ----------------
__device__ __forceinline__ void rownorm_t(float* X, int P, int off, float* red1,
                                          float* red2, float* rowM, float* rowR,
                                          int tid) {
    int r = tid >> 3, part = tid & 7;
    float* base = X + r * P + off + part * 32;
    float s1 = 0.f, s2 = 0.f;
#pragma unroll
    for (int j = 0; j < 8; j++) {
        float4 v = *(float4*)(base + 4 * j);
        s1 += (v.x + v.y) + (v.z + v.w);
        s2 += (v.x * v.x + v.y * v.y) + (v.z * v.z + v.w * v.w);
    }
    red1[tid] = s1;
    red2[tid] = s2;
    __syncthreads();
    if (tid < 32) {
        float a = 0.f, bq = 0.f;
#pragma unroll
        for (int p = 0; p < 8; p++) {
            a += red1[tid * 8 + p];
            bq += red2[tid * 8 + p];
        }
        float m = a * (1.f / 256.f);
        float var = bq * (1.f / 256.f) - m * m;
        rowM[tid] = m;
        rowR[tid] = rsqrtf(var + 1e-5f);
    }
    __syncthreads();
    float m = rowM[r], rs = rowR[r];
#pragma unroll
    for (int j = 0; j < 8; j++) {
        float4 v = *(float4*)(base + 4 * j);
        v.x = (v.x - m) * rs;
        v.y = (v.y - m) * rs;
        v.z = (v.z - m) * rs;
        v.w = (v.w - m) * rs;
        *(float4*)(base + 4 * j) = v;
    }
    __syncthreads();
}

// ---------------- GEMM, K-pair packed f32x2 ----------------
// src row-major [32][srcP], dst row-major [32][dstP]+dstOff.
// Wt global transposed [256 c][4*KP4 k]. 8-k double-buffered smem tiles.
// acc[i][c] packs (even-k, odd-k) partial sums; epilogue adds halves.
// act: 0 relu+bias, 1 leaky+bias, 2 scale by invs[row]
__device__ __forceinline__ void gemm_t(const float* __restrict__ src, int srcP,
                                       float* __restrict__ dst, int dstP, int dstOff,
                                       const float* __restrict__ Wt, int KP4,
                                       const float* __restrict__ bias,
                                       const float* __restrict__ invs,
                                       float* W0, float* W1, int Ktiles, int act,
                                       int tid) {
    int tr = tid >> 6;  // 0..3 -> rows 8*tr..8*tr+7
    int tc = tid & 63;  // cols tc + 64c
    ull acc[8][4];
#pragma unroll
    for (int i = 0; i < 8; i++)
#pragma unroll
        for (int c = 0; c < 4; c++) acc[i][c] = 0ull;

    const float4* Wt4 = (const float4*)Wt;
    int sc = tid >> 1, sq = tid & 1;
    float4 stg0, stg1;

    // prologue: tile0 -> W0, prefetch tile1 -> regs
    stg0 = Wt4[sc * KP4 + sq];
    stg1 = Wt4[(sc + 128) * KP4 + sq];
    ((float4*)W0)[sc * 3 + sq] = stg0;
    ((float4*)W0)[(sc + 128) * 3 + sq] = stg1;
    if (Ktiles > 1) {
        stg0 = Wt4[sc * KP4 + 2 + sq];
        stg1 = Wt4[(sc + 128) * KP4 + 2 + sq];
    }
    __syncthreads();

    for (int kt = 0; kt < Ktiles; kt++) {
        float* cur = (kt & 1) ? W1 : W0;
        float* nxt = (kt & 1) ? W0 : W1;
        if (kt + 1 < Ktiles) {
            ((float4*)nxt)[sc * 3 + sq] = stg0;
            ((float4*)nxt)[(sc + 128) * 3 + sq] = stg1;
            if (kt + 2 < Ktiles) {
                stg0 = Wt4[sc * KP4 + (kt + 2) * 2 + sq];
                stg1 = Wt4[(sc + 128) * KP4 + (kt + 2) * 2 + sq];
            }
        }
        const float* xb = src + (8 * tr) * srcP + kt * 8;
#pragma unroll
        for (int kg = 0; kg < 2; kg++) {
            ull xp01[8], xp23[8];
#pragma unroll
            for (int i = 0; i < 8; i++) {
                float4 q = *(const float4*)(xb + i * srcP + kg * 4);  // warp-uniform
                xp01[i] = pk2(q.x, q.y);
                xp23[i] = pk2(q.z, q.w);
            }
#pragma unroll
            for (int c = 0; c < 4; c++) {
                float4 w = *(const float4*)(cur + (tc + 64 * c) * KTP + kg * 4);
                ull w01 = pk2(w.x, w.y);
                ull w23 = pk2(w.z, w.w);
#pragma unroll
                for (int i = 0; i < 8; i++) {
                    acc[i][c] = fma2(xp01[i], w01, acc[i][c]);
                    acc[i][c] = fma2(xp23[i], w23, acc[i][c]);
                }
            }
        }
        __syncthreads();
    }

    // epilogue
#pragma unroll
    for (int c = 0; c < 4; c++) {
        int col = tc + 64 * c;
        float bb = (act != 2) ? __ldg(bias + col) : 0.f;
#pragma unroll
        for (int i = 0; i < 8; i++) {
            float lo, hi;
            upk2(acc[i][c], lo, hi);
            float y = lo + hi;
            if (act == 2) {
                y *= invs[8 * tr + i];
            } else {
                y += bb;
                y = (act == 0) ? fmaxf(y, 0.f) : ((y > 0.f) ? y : 0.01f * y);
            }
            dst[(8 * tr + i) * dstP + dstOff + col] = y;
        }
    }
    __syncthreads();
}

// ---------------- prep: transpose weights / vf into device globals ----------------
__global__ void prep_kernel(const float* __restrict__ cW, const float* __restrict__ w1,
                            const float* __restrict__ w2a, const float* __restrict__ w2b,
                            const float* __restrict__ vf) {
    int i = blockIdx.x * 256 + threadIdx.x;
    if (i < 92160) {
        int c = i / 360, k = i - 360 * c;
        g_cWt[i] = (k < 356) ? cW[k * 256 + c] : 0.f;
        return;
    }
    i -= 92160;
    if (i < 65536) { g_w1t[i] = w1[((i & 255) << 8) + (i >> 8)]; return; }
    i -= 65536;
    if (i < 65536) { g_w2at[i] = w2a[((i & 255) << 8) + (i >> 8)]; return; }
    i -= 65536;
    if (i < 65536) { g_w2bt[i] = w2b[((i & 255) << 8) + (i >> 8)]; return; }
    i -= 65536;
    if (i < 98304) {
        int b = i / 12288, r = i - b * 12288;
        int g = r / 48, a = r - 48 * g;
        g_vft[i] = vf[b * 12288 + a * 256 + g];
    }
}

// ---------------- main fused kernel: one CTA = 32 subset rows of one batch ----------------
__global__ void __launch_bounds__(TH, 2)
fused_main(const float* __restrict__ vmask, const float* __restrict__ eoh_g,
           const int* __restrict__ subs, const float* __restrict__ cB,
           const float* __restrict__ b1, const float* __restrict__ b2a,
           const float* __restrict__ b2b, const float* __restrict__ sW,
           const float* __restrict__ sB) {
    extern __shared__ float sm[];
    float* XA = sm;                   // 32*360 = 11520
    float* XB = sm + 11520;           // 32*260 = 8320
    float* W0 = sm + 19840;           // 256*12 = 3072
    float* W1 = sm + 22912;           // 3072
    float* red1 = sm + 25984;         // 256
    float* red2 = sm + 26240;         // 256
    float* rowM = sm + 26496;         // 32
    float* rowR = sm + 26528;         // 32
    float* invs = sm + 26560;         // 32
    float* maskv = sm + 26592;        // 48
    float* msq = sm + 26640;          // 48
    float* eoh = sm + 26688;          // 240 -> total 26928 floats

    int tid = threadIdx.x;
    int b = blockIdx.x >> 7;            // 128 tiles per batch
    int s0 = (blockIdx.x & 127) * MT;

    float* SRAW = W0;  // raw subset tile [32*48] packed (1536 <= 3072)
    float* SX = XB;    // masked X for stage A, row-major pitch 48 (1536 <= 8320)

    // ---- loads ----
    if (tid < 48) {
        float m = vmask[b * 48 + tid];
        maskv[tid] = m;
        msq[tid] = m * m;
    }
    if (tid < 240) eoh[tid] = eoh_g[b * 240 + tid];
    {
        const int* sb = subs + (b * 4096 + s0) * 48;
        for (int idx = tid; idx < 1536; idx += TH) SRAW[idx] = (float)sb[idx];
    }
    __syncthreads();

    // ---- counts (160 thr) + subset size (32 thr) ----
    if (tid < 160) {
        int r = tid / 5, e = tid - 5 * (tid / 5);
        float c = 0.f;
        for (int a = 0; a < 48; a++) c += SRAW[r * 48 + a] * eoh[a * 5 + e];
        red2[tid] = c;
    } else if (tid < 192) {
        int r = tid - 160;
        float sz = 0.f;
        for (int a = 0; a < 48; a++) sz += SRAW[r * 48 + a] * maskv[a];
        invs[r] = 1.f / (sz + 1e-4f);
    }
    __syncthreads();

    // ---- thermometer rows + K-pad + SX = s*m^2 ----
    if (tid < 32) {
        int r = tid;
        float cnt[5];
#pragma unroll
        for (int e = 0; e < 5; e++) cnt[e] = red2[r * 5 + e];
        float* xr = XA + r * XAP;
#pragma unroll
        for (int e = 0; e < 5; e++)
            for (int j = 0; j < 20; j++)
                xr[e * 20 + j] = ((float)j < cnt[e]) ? 1.f : 0.f;
        xr[356] = 0.f; xr[357] = 0.f; xr[358] = 0.f; xr[359] = 0.f;
    }
    for (int idx = tid; idx < 1536; idx += TH) {
        int a = idx - 48 * (idx / 48);
        SX[idx] = SRAW[idx] * msq[a];
    }
    __syncthreads();

    // ---- stage A: meanfeat = (SX @ vf_t) * invs -> XA cols 100..355 ----
    gemm_t(SX, 48, XA, XAP, 100, g_vft + b * 12288, 12, 0, invs, W0, W1, 6, 2, tid);

    rownorm_t(XA, XAP, 100, red1, red2, rowM, rowR, tid);            // subset_weighted_norm
    gemm_t(XA, XAP, XB, XBP, 0, g_cWt, 90, cB, 0, W0, W1, 45, 0, tid);   // combine + relu
    rownorm_t(XB, XBP, 0, red1, red2, rowM, rowR, tid);              // norm_post_combine
    gemm_t(XB, XBP, XA, XAP, 0, g_w1t, 64, b1, 0, W0, W1, 32, 0, tid);   // l1 + relu
    gemm_t(XA, XAP, XB, XBP, 0, g_w2at, 64, b2a, 0, W0, W1, 32, 1, tid); // l2a + leaky
    gemm_t(XB, XBP, XA, XAP, 0, g_w2bt, 64, b2b, 0, W0, W1, 32, 0, tid); // l2b: leaky+relu==relu
    rownorm_t(XA, XAP, 0, red1, red2, rowM, rowR, tid);              // norm_pre_score

    // ---- score head ----
    {
        int r = tid >> 3, part = tid & 7;
        const float* xr = XA + r * XAP + part * 32;
        float s = 0.f;
#pragma unroll
        for (int j = 0; j < 8; j++) {
            float4 x = *(const float4*)(xr + 4 * j);
            float4 w = __ldg((const float4*)(sW + part * 32 + 4 * j));
            s += x.x * w.x + x.y * w.y + x.z * w.z + x.w * w.w;
        }
        red1[tid] = s;
        __syncthreads();
        if (tid < 32) {
            float t = 0.f;
#pragma unroll
            for (int p = 0; p < 8; p++) t += red1[tid * 8 + p];
            g_scores[b * 4096 + s0 + tid] = t + __ldg(sB);
        }
    }
}

// ---------------- per-batch softmax over 4096 scores ----------------
__global__ void softmax_kernel(float* __restrict__ probs_out) {
    __shared__ float sbuf[32];
    __shared__ float sval;
    int b = blockIdx.x, t = threadIdx.x, lane = t & 31, wid = t >> 5;
    const float* sc = g_scores + b * 4096;
    float v0 = sc[t], v1 = sc[t + 1024], v2 = sc[t + 2048], v3 = sc[t + 3072];
    float mx = fmaxf(fmaxf(v0, v1), fmaxf(v2, v3));
#pragma unroll
    for (int o = 16; o; o >>= 1) mx = fmaxf(mx, __shfl_xor_sync(0xffffffffu, mx, o));
    if (lane == 0) sbuf[wid] = mx;
    __syncthreads();
    if (t < 32) {
        float m = sbuf[t];
#pragma unroll
        for (int o = 16; o; o >>= 1) m = fmaxf(m, __shfl_xor_sync(0xffffffffu, m, o));
        if (t == 0) sval = m;
    }
    __syncthreads();
    mx = sval;
    float e0 = expf(v0 - mx), e1 = expf(v1 - mx), e2 = expf(v2 - mx), e3 = expf(v3 - mx);
    float sum = e0 + e1 + e2 + e3;
#pragma unroll
    for (int o = 16; o; o >>= 1) sum += __shfl_xor_sync(0xffffffffu, sum, o);
    __syncthreads();
    if (lane == 0) sbuf[wid] = sum;
    __syncthreads();
    if (t < 32) {
        float s = sbuf[t];
#pragma unroll
        for (int o = 16; o; o >>= 1) s += __shfl_xor_sync(0xffffffffu, s, o);
        if (t == 0) sval = s;
    }
    __syncthreads();
    float inv = 1.f / sval;
    float p0 = e0 * inv, p1 = e1 * inv, p2 = e2 * inv, p3 = e3 * inv;
    probs_out[b * 4096 + t] = p0;
    probs_out[b * 4096 + t + 1024] = p1;
    probs_out[b * 4096 + t + 2048] = p2;
    probs_out[b * 4096 + t + 3072] = p3;
    g_probs[b * 4096 + t] = p0;
    g_probs[b * 4096 + t + 1024] = p1;
    g_probs[b * 4096 + t + 2048] = p2;
    g_probs[b * 4096 + t + 3072] = p3;
}

// ---------------- zero + scatter into spectral bins ----------------
__global__ void zero_kernel(float* __restrict__ p, int n) {
    int idx = blockIdx.x * blockDim.x + threadIdx.x;
    if (idx < n) p[idx] = 0.f;
}

__global__ void scatter_kernel(const int* __restrict__ midx,
                               const float* __restrict__ inten,
                               float* __restrict__ spect) {
    int idx = blockIdx.x * blockDim.x + threadIdx.x;
    if (idx >= 8 * 4096 * 32) return;
    int b = idx >> 17;
    int s = (idx >> 5) & 4095;
    float w = inten[idx] * g_probs[b * 4096 + s];
    atomicAdd(spect + b * 65536 + midx[idx], w);
}

// ---------------- launch ----------------
extern "C" void kernel_launch(void* const* d_in, const int* in_sizes, int n_in,
                              void* d_out, int out_size) {
    const float* vf    = (const float*)d_in[0];
    const float* vmask = (const float*)d_in[1];
    const float* eoh   = (const float*)d_in[2];
    const int*   subs  = (const int*)d_in[4];
    const int*   midx  = (const int*)d_in[6];
    const float* inten = (const float*)d_in[7];
    const float* cW    = (const float*)d_in[8];
    const float* cB    = (const float*)d_in[9];
    const float* w1    = (const float*)d_in[10];
    const float* b1    = (const float*)d_in[11];
    const float* w2a   = (const float*)d_in[12];
    const float* b2a   = (const float*)d_in[13];
    const float* w2b   = (const float*)d_in[14];
    const float* b2b   = (const float*)d_in[15];
    const float* sW    = (const float*)d_in[16];
    const float* sB    = (const float*)d_in[17];
    float* out = (float*)d_out;

    int pOff = out_size - 8 * 4096;  // spect first, probs second
    size_t smem = (size_t)26928 * sizeof(float);
    cudaFuncSetAttribute(fused_main, cudaFuncAttributeMaxDynamicSharedMemorySize,
                         (int)smem);

    prep_kernel<<<1512, 256>>>(cW, w1, w2a, w2b, vf);
    zero_kernel<<<(pOff + 511) / 512, 512>>>(out, pOff);
    fused_main<<<1024, TH, smem>>>(vmask, eoh, subs, cB, b1, b2a, b2b, sW, sB);
    softmax_kernel<<<8, 1024>>>(out + pOff);
    scatter_kernel<<<2048, 512>>>(midx, inten, out);
}

// round 10
// speedup vs baseline: 1.0759x; 1.0759x over previous
#include <cuda_runtime.h>
#include <cuda_bf16.h>

#define TH 256
#define MT 32
#define XAP 360   // XA row pitch (K up to 360)
#define XBP 260   // XB row pitch
#define KTP 12    // W tile k-pitch: 8 k + 4 pad (stride 3 float4 -> conflict-free)

// ---------------- device globals (no allocs allowed) ----------------
__device__ float g_scores[8 * 4096];
__device__ float g_probs[8 * 4096];
__device__ float g_cWt[256 * 360];    // combine W transposed [c][k], k padded to 360
__device__ float g_w1t[256 * 256];
__device__ float g_w2at[256 * 256];
__device__ float g_w2bt[256 * 256];
__device__ float g_vft[8 * 256 * 48]; // vf transposed per batch [b][g][a]

typedef unsigned long long ull;

__device__ __forceinline__ ull pk2(float a, float b) {
    ull r;
    asm("mov.b64 %0, {%1,%2};" : "=l"(r) : "f"(a), "f"(b));
    return r;
}
__device__ __forceinline__ void upk2(ull v, float& a, float& b) {
    asm("mov.b64 {%0,%1}, %2;" : "=f"(a), "=f"(b) : "l"(v));
}
__device__ __forceinline__ ull fma2(ull a, ull b, ull c) {
    ull d;
    asm("fma.rn.f32x2 %0, %1, %2, %3;" : "=l"(d) : "l"(a), "l"(b), "l"(c));
    return d;
}

// ---------------- row-wise instance norm over 256 dims, row-major X ----------------
__device__ __forceinline__ void rownorm_t(float* X, int P, int off, float* red1,
                                          float* red2, float* rowM, float* rowR,
                                          int tid) {
    int r = tid >> 3, part = tid & 7;
    float* base = X + r * P + off + part * 32;
    float s1 = 0.f, s2 = 0.f;
#pragma unroll
    for (int j = 0; j < 8; j++) {
        float4 v = *(float4*)(base + 4 * j);
        s1 += (v.x + v.y) + (v.z + v.w);
        s2 += (v.x * v.x + v.y * v.y) + (v.z * v.z + v.w * v.w);
    }
    red1[tid] = s1;
    red2[tid] = s2;
    __syncthreads();
    if (tid < 32) {
        float a = 0.f, bq = 0.f;
#pragma unroll
        for (int p = 0; p < 8; p++) {
            a += red1[tid * 8 + p];
            bq += red2[tid * 8 + p];
        }
        float m = a * (1.f / 256.f);
        float var = bq * (1.f / 256.f) - m * m;
        rowM[tid] = m;
        rowR[tid] = rsqrtf(var + 1e-5f);
    }
    __syncthreads();
    float m = rowM[r], rs = rowR[r];
#pragma unroll
    for (int j = 0; j < 8; j++) {
        float4 v = *(float4*)(base + 4 * j);
        v.x = (v.x - m) * rs;
        v.y = (v.y - m) * rs;
        v.z = (v.z - m) * rs;
        v.w = (v.w - m) * rs;
        *(float4*)(base + 4 * j) = v;
    }
    __syncthreads();
}

// ---------------- GEMM, K-pair packed f32x2, register-lean inner loop ----------------
// src row-major [32][srcP], dst row-major [32][dstP]+dstOff.
// Wt global transposed [256 c][4*KP4 k]. 8-k double-buffered smem tiles.
// acc[i][c] packs (even-k, odd-k) partial sums; epilogue adds halves.
// act: 0 relu+bias, 1 leaky+bias, 2 scale by invs[row]
__device__ __forceinline__ void gemm_t(const float* __restrict__ src, int srcP,
                                       float* __restrict__ dst, int dstP, int dstOff,
                                       const float* __restrict__ Wt, int KP4,
                                       const float* __restrict__ bias,
                                       const float* __restrict__ invs,
                                       float* W0, float* W1, int Ktiles, int act,
                                       int tid) {
    int tr = tid >> 6;  // 0..3 -> rows 8*tr..8*tr+7
    int tc = tid & 63;  // cols tc + 64c
    ull acc[8][4];
#pragma unroll
    for (int i = 0; i < 8; i++)
#pragma unroll
        for (int c = 0; c < 4; c++) acc[i][c] = 0ull;

    const float4* Wt4 = (const float4*)Wt;
    int sc = tid >> 1, sq = tid & 1;
    float4 stg0, stg1;

    // prologue: tile0 -> W0, prefetch tile1 -> regs
    stg0 = Wt4[sc * KP4 + sq];
    stg1 = Wt4[(sc + 128) * KP4 + sq];
    ((float4*)W0)[sc * 3 + sq] = stg0;
    ((float4*)W0)[(sc + 128) * 3 + sq] = stg1;
    if (Ktiles > 1) {
        stg0 = Wt4[sc * KP4 + 2 + sq];
        stg1 = Wt4[(sc + 128) * KP4 + 2 + sq];
    }
    __syncthreads();

    for (int kt = 0; kt < Ktiles; kt++) {
        float* cur = (kt & 1) ? W1 : W0;
        float* nxt = (kt & 1) ? W0 : W1;
        if (kt + 1 < Ktiles) {
            ((float4*)nxt)[sc * 3 + sq] = stg0;
            ((float4*)nxt)[(sc + 128) * 3 + sq] = stg1;
            if (kt + 2 < Ktiles) {
                stg0 = Wt4[sc * KP4 + (kt + 2) * 2 + sq];
                stg1 = Wt4[(sc + 128) * KP4 + (kt + 2) * 2 + sq];
            }
        }
        const float* xb = src + (8 * tr) * srcP + kt * 8;
        const float* wb = cur + tc * KTP;
#pragma unroll
        for (int kg = 0; kg < 2; kg++) {
            // 4 column weight-pairs for this k-quad (16 regs, kg-scoped)
            float4 wv0 = *(const float4*)(wb + kg * 4);
            float4 wv1 = *(const float4*)(wb + 64 * KTP + kg * 4);
            float4 wv2 = *(const float4*)(wb + 128 * KTP + kg * 4);
            float4 wv3 = *(const float4*)(wb + 192 * KTP + kg * 4);
            ull w0a = pk2(wv0.x, wv0.y), w0b = pk2(wv0.z, wv0.w);
            ull w1a = pk2(wv1.x, wv1.y), w1b = pk2(wv1.z, wv1.w);
            ull w2a = pk2(wv2.x, wv2.y), w2b = pk2(wv2.z, wv2.w);
            ull w3a = pk2(wv3.x, wv3.y), w3b = pk2(wv3.z, wv3.w);
#pragma unroll
            for (int i = 0; i < 8; i++) {
                float4 q = *(const float4*)(xb + i * srcP + kg * 4);  // warp-uniform
                ull x01 = pk2(q.x, q.y);
                ull x23 = pk2(q.z, q.w);
                acc[i][0] = fma2(x01, w0a, acc[i][0]);
                acc[i][0] = fma2(x23, w0b, acc[i][0]);
                acc[i][1] = fma2(x01, w1a, acc[i][1]);
                acc[i][1] = fma2(x23, w1b, acc[i][1]);
                acc[i][2] = fma2(x01, w2a, acc[i][2]);
                acc[i][2] = fma2(x23, w2b, acc[i][2]);
                acc[i][3] = fma2(x01, w3a, acc[i][3]);
                acc[i][3] = fma2(x23, w3b, acc[i][3]);
            }
        }
        __syncthreads();
    }

    // epilogue
#pragma unroll
    for (int c = 0; c < 4; c++) {
        int col = tc + 64 * c;
        float bb = (act != 2) ? __ldg(bias + col) : 0.f;
#pragma unroll
        for (int i = 0; i < 8; i++) {
            float lo, hi;
            upk2(acc[i][c], lo, hi);
            float y = lo + hi;
            if (act == 2) {
                y *= invs[8 * tr + i];
            } else {
                y += bb;
                y = (act == 0) ? fmaxf(y, 0.f) : ((y > 0.f) ? y : 0.01f * y);
            }
            dst[(8 * tr + i) * dstP + dstOff + col] = y;
        }
    }
    __syncthreads();
}

// ---------------- prep: transpose weights / vf into device globals ----------------
__global__ void prep_kernel(const float* __restrict__ cW, const float* __restrict__ w1,
                            const float* __restrict__ w2a, const float* __restrict__ w2b,
                            const float* __restrict__ vf) {
    int i = blockIdx.x * 256 + threadIdx.x;
    if (i < 92160) {
        int c = i / 360, k = i - 360 * c;
        g_cWt[i] = (k < 356) ? cW[k * 256 + c] : 0.f;
        return;
    }
    i -= 92160;
    if (i < 65536) { g_w1t[i] = w1[((i & 255) << 8) + (i >> 8)]; return; }
    i -= 65536;
    if (i < 65536) { g_w2at[i] = w2a[((i & 255) << 8) + (i >> 8)]; return; }
    i -= 65536;
    if (i < 65536) { g_w2bt[i] = w2b[((i & 255) << 8) + (i >> 8)]; return; }
    i -= 65536;
    if (i < 98304) {
        int b = i / 12288, r = i - b * 12288;
        int g = r / 48, a = r - 48 * g;
        g_vft[i] = vf[b * 12288 + a * 256 + g];
    }
}

// ---------------- main fused kernel: one CTA = 32 subset rows of one batch ----------------
__global__ void __launch_bounds__(TH, 2)
fused_main(const float* __restrict__ vmask, const float* __restrict__ eoh_g,
           const int* __restrict__ subs, const float* __restrict__ cB,
           const float* __restrict__ b1, const float* __restrict__ b2a,
           const float* __restrict__ b2b, const float* __restrict__ sW,
           const float* __restrict__ sB) {
    extern __shared__ float sm[];
    float* XA = sm;                   // 32*360 = 11520
    float* XB = sm + 11520;           // 32*260 = 8320
    float* W0 = sm + 19840;           // 256*12 = 3072
    float* W1 = sm + 22912;           // 3072
    float* red1 = sm + 25984;         // 256
    float* red2 = sm + 26240;         // 256
    float* rowM = sm + 26496;         // 32
    float* rowR = sm + 26528;         // 32
    float* invs = sm + 26560;         // 32
    float* maskv = sm + 26592;        // 48
    float* msq = sm + 26640;          // 48
    float* eoh = sm + 26688;          // 240 -> total 26928 floats

    int tid = threadIdx.x;
    int b = blockIdx.x >> 7;            // 128 tiles per batch
    int s0 = (blockIdx.x & 127) * MT;

    float* SRAW = W0;  // raw subset tile [32*48] packed (1536 <= 3072)
    float* SX = XB;    // masked X for stage A, row-major pitch 48 (1536 <= 8320)

    // ---- loads ----
    if (tid < 48) {
        float m = vmask[b * 48 + tid];
        maskv[tid] = m;
        msq[tid] = m * m;
    }
    if (tid < 240) eoh[tid] = eoh_g[b * 240 + tid];
    {
        const int* sb = subs + (b * 4096 + s0) * 48;
        for (int idx = tid; idx < 1536; idx += TH) SRAW[idx] = (float)sb[idx];
    }
    __syncthreads();

    // ---- counts (160 thr) + subset size (32 thr) ----
    if (tid < 160) {
        int r = tid / 5, e = tid - 5 * (tid / 5);
        float c = 0.f;
        for (int a = 0; a < 48; a++) c += SRAW[r * 48 + a] * eoh[a * 5 + e];
        red2[tid] = c;
    } else if (tid < 192) {
        int r = tid - 160;
        float sz = 0.f;
        for (int a = 0; a < 48; a++) sz += SRAW[r * 48 + a] * maskv[a];
        invs[r] = 1.f / (sz + 1e-4f);
    }
    __syncthreads();

    // ---- thermometer rows + K-pad + SX = s*m^2 ----
    if (tid < 32) {
        int r = tid;
        float cnt[5];
#pragma unroll
        for (int e = 0; e < 5; e++) cnt[e] = red2[r * 5 + e];
        float* xr = XA + r * XAP;
#pragma unroll
        for (int e = 0; e < 5; e++)
            for (int j = 0; j < 20; j++)
                xr[e * 20 + j] = ((float)j < cnt[e]) ? 1.f : 0.f;
        xr[356] = 0.f; xr[357] = 0.f; xr[358] = 0.f; xr[359] = 0.f;
    }
    for (int idx = tid; idx < 1536; idx += TH) {
        int a = idx - 48 * (idx / 48);
        SX[idx] = SRAW[idx] * msq[a];
    }
    __syncthreads();

    // ---- stage A: meanfeat = (SX @ vf_t) * invs -> XA cols 100..355 ----
    gemm_t(SX, 48, XA, XAP, 100, g_vft + b * 12288, 12, 0, invs, W0, W1, 6, 2, tid);

    rownorm_t(XA, XAP, 100, red1, red2, rowM, rowR, tid);            // subset_weighted_norm
    gemm_t(XA, XAP, XB, XBP, 0, g_cWt, 90, cB, 0, W0, W1, 45, 0, tid);   // combine + relu
    rownorm_t(XB, XBP, 0, red1, red2, rowM, rowR, tid);              // norm_post_combine
    gemm_t(XB, XBP, XA, XAP, 0, g_w1t, 64, b1, 0, W0, W1, 32, 0, tid);   // l1 + relu
    gemm_t(XA, XAP, XB, XBP, 0, g_w2at, 64, b2a, 0, W0, W1, 32, 1, tid); // l2a + leaky
    gemm_t(XB, XBP, XA, XAP, 0, g_w2bt, 64, b2b, 0, W0, W1, 32, 0, tid); // l2b: leaky+relu==relu
    rownorm_t(XA, XAP, 0, red1, red2, rowM, rowR, tid);              // norm_pre_score

    // ---- score head ----
    {
        int r = tid >> 3, part = tid & 7;
        const float* xr = XA + r * XAP + part * 32;
        float s = 0.f;
#pragma unroll
        for (int j = 0; j < 8; j++) {
            float4 x = *(const float4*)(xr + 4 * j);
            float4 w = __ldg((const float4*)(sW + part * 32 + 4 * j));
            s += x.x * w.x + x.y * w.y + x.z * w.z + x.w * w.w;
        }
        red1[tid] = s;
        __syncthreads();
        if (tid < 32) {
            float t = 0.f;
#pragma unroll
            for (int p = 0; p < 8; p++) t += red1[tid * 8 + p];
            g_scores[b * 4096 + s0 + tid] = t + __ldg(sB);
        }
    }
}

// ---------------- per-batch softmax over 4096 scores ----------------
__global__ void softmax_kernel(float* __restrict__ probs_out) {
    __shared__ float sbuf[32];
    __shared__ float sval;
    int b = blockIdx.x, t = threadIdx.x, lane = t & 31, wid = t >> 5;
    const float* sc = g_scores + b * 4096;
    float v0 = sc[t], v1 = sc[t + 1024], v2 = sc[t + 2048], v3 = sc[t + 3072];
    float mx = fmaxf(fmaxf(v0, v1), fmaxf(v2, v3));
#pragma unroll
    for (int o = 16; o; o >>= 1) mx = fmaxf(mx, __shfl_xor_sync(0xffffffffu, mx, o));
    if (lane == 0) sbuf[wid] = mx;
    __syncthreads();
    if (t < 32) {
        float m = sbuf[t];
#pragma unroll
        for (int o = 16; o; o >>= 1) m = fmaxf(m, __shfl_xor_sync(0xffffffffu, m, o));
        if (t == 0) sval = m;
    }
    __syncthreads();
    mx = sval;
    float e0 = expf(v0 - mx), e1 = expf(v1 - mx), e2 = expf(v2 - mx), e3 = expf(v3 - mx);
    float sum = e0 + e1 + e2 + e3;
#pragma unroll
    for (int o = 16; o; o >>= 1) sum += __shfl_xor_sync(0xffffffffu, sum, o);
    __syncthreads();
    if (lane == 0) sbuf[wid] = sum;
    __syncthreads();
    if (t < 32) {
        float s = sbuf[t];
#pragma unroll
        for (int o = 16; o; o >>= 1) s += __shfl_xor_sync(0xffffffffu, s, o);
        if (t == 0) sval = s;
    }
    __syncthreads();
    float inv = 1.f / sval;
    float p0 = e0 * inv, p1 = e1 * inv, p2 = e2 * inv, p3 = e3 * inv;
    probs_out[b * 4096 + t] = p0;
    probs_out[b * 4096 + t + 1024] = p1;
    probs_out[b * 4096 + t + 2048] = p2;
    probs_out[b * 4096 + t + 3072] = p3;
    g_probs[b * 4096 + t] = p0;
    g_probs[b * 4096 + t + 1024] = p1;
    g_probs[b * 4096 + t + 2048] = p2;
    g_probs[b * 4096 + t + 3072] = p3;
}

// ---------------- zero + scatter into spectral bins ----------------
__global__ void zero_kernel(float* __restrict__ p, int n) {
    int idx = blockIdx.x * blockDim.x + threadIdx.x;
    if (idx < n) p[idx] = 0.f;
}

__global__ void scatter_kernel(const int* __restrict__ midx,
                               const float* __restrict__ inten,
                               float* __restrict__ spect) {
    int idx = blockIdx.x * blockDim.x + threadIdx.x;
    if (idx >= 8 * 4096 * 32) return;
    int b = idx >> 17;
    int s = (idx >> 5) & 4095;
    float w = inten[idx] * g_probs[b * 4096 + s];
    atomicAdd(spect + b * 65536 + midx[idx], w);
}

// ---------------- launch ----------------
extern "C" void kernel_launch(void* const* d_in, const int* in_sizes, int n_in,
                              void* d_out, int out_size) {
    const float* vf    = (const float*)d_in[0];
    const float* vmask = (const float*)d_in[1];
    const float* eoh   = (const float*)d_in[2];
    const int*   subs  = (const int*)d_in[4];
    const int*   midx  = (const int*)d_in[6];
    const float* inten = (const float*)d_in[7];
    const float* cW    = (const float*)d_in[8];
    const float* cB    = (const float*)d_in[9];
    const float* w1    = (const float*)d_in[10];
    const float* b1    = (const float*)d_in[11];
    const float* w2a   = (const float*)d_in[12];
    const float* b2a   = (const float*)d_in[13];
    const float* w2b   = (const float*)d_in[14];
    const float* b2b   = (const float*)d_in[15];
    const float* sW    = (const float*)d_in[16];
    const float* sB    = (const float*)d_in[17];
    float* out = (float*)d_out;

    int pOff = out_size - 8 * 4096;  // spect first, probs second
    size_t smem = (size_t)26928 * sizeof(float);
    cudaFuncSetAttribute(fused_main, cudaFuncAttributeMaxDynamicSharedMemorySize,
                         (int)smem);

    prep_kernel<<<1512, 256>>>(cW, w1, w2a, w2b, vf);
    zero_kernel<<<(pOff + 511) / 512, 512>>>(out, pOff);
    fused_main<<<1024, TH, smem>>>(vmask, eoh, subs, cB, b1, b2a, b2b, sW, sB);
    softmax_kernel<<<8, 1024>>>(out + pOff);
    scatter_kernel<<<2048, 512>>>(midx, inten, out);
}

// round 13
// speedup vs baseline: 1.5808x; 1.4693x over previous
#include <cuda_runtime.h>
#include <cuda_bf16.h>

#define TH 256
#define MT 32
#define PITCH 36    // 32 + 4: conflict-free, 144B col stride (16B aligned)
#define SUBP 49     // raw subset tile stride (odd -> conflict-free)

// ---------------- device globals (no allocs allowed) ----------------
__device__ float g_scores[8 * 4096];
__device__ float g_probs[8 * 4096];

typedef unsigned long long ull;

// ---------------- f32x2 helpers (sm_103a packed fp32 FMA) ----------------
__device__ __forceinline__ ull pk2(float a, float b) {
    ull r;
    asm("mov.b64 %0, {%1,%2};" : "=l"(r) : "f"(a), "f"(b));
    return r;
}
__device__ __forceinline__ void upk2(ull v, float& a, float& b) {
    asm("mov.b64 {%0,%1}, %2;" : "=f"(a), "=f"(b) : "l"(v));
}
__device__ __forceinline__ ull fma2(ull a, ull b, ull c) {
    ull d;
    asm("fma.rn.f32x2 %0, %1, %2, %3;" : "=l"(d) : "l"(a), "l"(b), "l"(c));
    return d;
}

// ---------------- row-wise instance norm over 256 dims, 32 rows ----------------
// X layout: X[k*PITCH + r], k in [0,256), r in [0,32)
__device__ __forceinline__ void rownorm(float* X, float* red1, float* red2,
                                        float* rowM, float* rowR, int tid) {
    int r = tid & 31, part = tid >> 5;  // 8 parts x 32 cols
    float s1 = 0.f, s2 = 0.f;
    const float* base = X + (part * 32) * PITCH + r;
#pragma unroll
    for (int g = 0; g < 32; g++) {
        float v = base[g * PITCH];
        s1 += v;
        s2 += v * v;
    }
    red1[part * 32 + r] = s1;
    red2[part * 32 + r] = s2;
    __syncthreads();
    if (tid < 32) {
        float a = 0.f, bq = 0.f;
#pragma unroll
        for (int p = 0; p < 8; p++) {
            a += red1[p * 32 + tid];
            bq += red2[p * 32 + tid];
        }
        float m = a * (1.f / 256.f);
        float var = bq * (1.f / 256.f) - m * m;
        rowM[tid] = m;
        rowR[tid] = rsqrtf(var + 1e-5f);
    }
    __syncthreads();
#pragma unroll
    for (int i = 0; i < 32; i++) {
        int c = (tid >> 5) + i * 8, rr = tid & 31;
        float* p = X + c * PITCH + rr;
        *p = (*p - rowM[rr]) * rowR[rr];
    }
    __syncthreads();
}

// ---------------- tiled GEMM: Y[r][c] = act( sum_k X[k][r]*W[k][c] + b[c] ) ----------------
// src/dst col-major (PITCH). Double-buffered 8-row W tiles streamed from global
// in original [k][c] layout. Thread map: tg = tid>>7 (rows 16*tg..16*tg+15),
// tc = tid&127 (cols tc, tc+128). acc = 8 row-pairs x 2 cols = 16 ull (32 regs).
// X loads: 4 warp-uniform LDS.128 per k (pairs free). W: 2 LDS.32 + 2 dup MOVs.
// act: 0=relu+bias, 1=leaky(0.01)+bias, 2=scale by invs[row] (no bias/act)
__device__ __forceinline__ void mlp_gemm(const float* __restrict__ src,
                                         float* __restrict__ dst,
                                         const float* __restrict__ Wg,
                                         const float* __restrict__ bias,
                                         const float* __restrict__ invs,
                                         float* W0, float* W1, int Krows,
                                         int Ktiles, int act, int tid) {
    int tg = tid >> 7;   // 0..1 -> rows 16*tg..16*tg+15
    int tc = tid & 127;  // cols tc, tc+128
    ull acc[8][2];
#pragma unroll
    for (int i = 0; i < 8; i++) {
        acc[i][0] = 0ull;
        acc[i][1] = 0ull;
    }

    const float4* W4 = (const float4*)Wg;
    float4 stg[2];

    // prologue: tile0 -> W0, prefetch tile1 -> regs
#pragma unroll
    for (int i = 0; i < 2; i++) {
        int f4i = tid + TH * i;
        int row = f4i >> 6;
        stg[i] = make_float4(0.f, 0.f, 0.f, 0.f);
        if (row < Krows) stg[i] = W4[row * 64 + (f4i & 63)];
    }
#pragma unroll
    for (int i = 0; i < 2; i++) ((float4*)W0)[tid + TH * i] = stg[i];
    if (Ktiles > 1) {
#pragma unroll
        for (int i = 0; i < 2; i++) {
            int f4i = tid + TH * i;
            int row = (f4i >> 6) + 8;
            stg[i] = make_float4(0.f, 0.f, 0.f, 0.f);
            if (row < Krows) stg[i] = W4[row * 64 + (f4i & 63)];
        }
    }
    __syncthreads();

    for (int kt = 0; kt < Ktiles; kt++) {
        float* cur = (kt & 1) ? W1 : W0;
        float* nxt = (kt & 1) ? W0 : W1;
        if (kt + 1 < Ktiles) {
#pragma unroll
            for (int i = 0; i < 2; i++) ((float4*)nxt)[tid + TH * i] = stg[i];
            if (kt + 2 < Ktiles) {
#pragma unroll
                for (int i = 0; i < 2; i++) {
                    int f4i = tid + TH * i;
                    int row = (f4i >> 6) + (kt + 2) * 8;
                    stg[i] = make_float4(0.f, 0.f, 0.f, 0.f);
                    if (row < Krows) stg[i] = W4[row * 64 + (f4i & 63)];
                }
            }
        }
        const float* xbase = src + (kt * 8) * PITCH + 16 * tg;
#pragma unroll
        for (int k = 0; k < 8; k++) {
            const float* xk = xbase + k * PITCH;
            float4 xa = *(const float4*)(xk);       // warp-uniform broadcasts
            float4 xb = *(const float4*)(xk + 4);
            float4 xc = *(const float4*)(xk + 8);
            float4 xd = *(const float4*)(xk + 12);
            ull xp0 = pk2(xa.x, xa.y), xp1 = pk2(xa.z, xa.w);
            ull xp2 = pk2(xb.x, xb.y), xp3 = pk2(xb.z, xb.w);
            ull xp4 = pk2(xc.x, xc.y), xp5 = pk2(xc.z, xc.w);
            ull xp6 = pk2(xd.x, xd.y), xp7 = pk2(xd.z, xd.w);
            const float* wr = cur + k * 256 + tc;
            float w0 = wr[0];
            float w1 = wr[128];
            ull wd0 = pk2(w0, w0);
            ull wd1 = pk2(w1, w1);
            acc[0][0] = fma2(xp0, wd0, acc[0][0]);
            acc[1][0] = fma2(xp1, wd0, acc[1][0]);
            acc[2][0] = fma2(xp2, wd0, acc[2][0]);
            acc[3][0] = fma2(xp3, wd0, acc[3][0]);
            acc[4][0] = fma2(xp4, wd0, acc[4][0]);
            acc[5][0] = fma2(xp5, wd0, acc[5][0]);
            acc[6][0] = fma2(xp6, wd0, acc[6][0]);
            acc[7][0] = fma2(xp7, wd0, acc[7][0]);
            acc[0][1] = fma2(xp0, wd1, acc[0][1]);
            acc[1][1] = fma2(xp1, wd1, acc[1][1]);
            acc[2][1] = fma2(xp2, wd1, acc[2][1]);
            acc[3][1] = fma2(xp3, wd1, acc[3][1]);
            acc[4][1] = fma2(xp4, wd1, acc[4][1]);
            acc[5][1] = fma2(xp5, wd1, acc[5][1]);
            acc[6][1] = fma2(xp6, wd1, acc[6][1]);
            acc[7][1] = fma2(xp7, wd1, acc[7][1]);
        }
        __syncthreads();
    }

    // epilogue
#pragma unroll
    for (int c = 0; c < 2; c++) {
        int col = tc + 128 * c;
        float y[16];
        if (act == 2) {
#pragma unroll
            for (int rp = 0; rp < 8; rp++) {
                float lo, hi;
                upk2(acc[rp][c], lo, hi);
                y[2 * rp] = lo * invs[16 * tg + 2 * rp];
                y[2 * rp + 1] = hi * invs[16 * tg + 2 * rp + 1];
            }
        } else {
            float bb = __ldg(bias + col);
#pragma unroll
            for (int rp = 0; rp < 8; rp++) {
                float lo, hi;
                upk2(acc[rp][c], lo, hi);
                lo += bb;
                hi += bb;
                if (act == 0) {
                    lo = fmaxf(lo, 0.f);
                    hi = fmaxf(hi, 0.f);
                } else {
                    lo = (lo > 0.f) ? lo : 0.01f * lo;
                    hi = (hi > 0.f) ? hi : 0.01f * hi;
                }
                y[2 * rp] = lo;
                y[2 * rp + 1] = hi;
            }
        }
        float* dcol = dst + col * PITCH + 16 * tg;
        *(float4*)dcol = make_float4(y[0], y[1], y[2], y[3]);
        *(float4*)(dcol + 4) = make_float4(y[4], y[5], y[6], y[7]);
        *(float4*)(dcol + 8) = make_float4(y[8], y[9], y[10], y[11]);
        *(float4*)(dcol + 12) = make_float4(y[12], y[13], y[14], y[15]);
    }
    __syncthreads();
}

// ---------------- main fused kernel: one CTA = 32 subset rows of one batch ----------------
__global__ void __launch_bounds__(TH, 2)
fused_main(const float* __restrict__ vf, const float* __restrict__ vmask,
           const float* __restrict__ eoh_g, const int* __restrict__ subs,
           const float* __restrict__ cW, const float* __restrict__ cB,
           const float* __restrict__ w1, const float* __restrict__ b1,
           const float* __restrict__ w2a, const float* __restrict__ b2a,
           const float* __restrict__ w2b, const float* __restrict__ b2b,
           const float* __restrict__ sW, const float* __restrict__ sB) {
    extern __shared__ float sm[];
    float* XA = sm;                  // 360*36 = 12960 floats
    float* XB = sm + 12960;          // 256*36 = 9216
    float* W0 = sm + 22176;          // 8*256 = 2048
    float* W1 = sm + 24224;          // 2048
    float* red1 = sm + 26272;        // 256
    float* red2 = sm + 26528;        // 256
    float* rowM = sm + 26784;        // 32
    float* rowR = sm + 26816;        // 32
    float* invs = sm + 26848;        // 32
    float* maskv = sm + 26880;       // 48
    float* eoh = sm + 26928;         // 240  -> total 27168 floats (106.1 KB)

    int tid = threadIdx.x;
    int b = blockIdx.x >> 7;           // 128 tiles per batch
    int s0 = (blockIdx.x & 127) * MT;

    float* SUBR = W0;  // alias: raw subset tile [32][SUBP] = 1568 <= 4096 (W0+W1)

    // ---- loads: raw subsets (contiguous 1536 ints), mask, element one-hot ----
    for (int idx = tid; idx < MT * 48; idx += TH) {
        int r = idx / 48, a = idx - r * 48;
        SUBR[r * SUBP + a] = (float)subs[(b * 4096 + s0) * 48 + idx];
    }
    if (tid < 48) maskv[tid] = vmask[b * 48 + tid];
    if (tid < 240) eoh[tid] = eoh_g[b * 240 + tid];
    __syncthreads();

    // ---- counts (160 thr), subset size (32 thr) ----
    if (tid < 160) {
        int r = tid / 5, e = tid - 5 * (tid / 5);
        float c = 0.f;
        for (int a = 0; a < 48; a++) c += SUBR[r * SUBP + a] * eoh[a * 5 + e];
        red2[tid] = c;
    } else if (tid < 192) {
        int r = tid - 160;
        float sz = 0.f;
        for (int a = 0; a < 48; a++) sz += SUBR[r * SUBP + a] * maskv[a];
        invs[r] = 1.f / (sz + 1e-4f);
    }
    __syncthreads();

    // ---- thermometer rows 0..99 ; X = (s * m^2) k-major into XB ; zero pad rows ----
    if (tid < 32) {
        int r = tid;
        float cnt[5];
#pragma unroll
        for (int e = 0; e < 5; e++) cnt[e] = red2[r * 5 + e];
#pragma unroll
        for (int e = 0; e < 5; e++)
            for (int j = 0; j < 20; j++)
                XA[(e * 20 + j) * PITCH + r] = ((float)j < cnt[e]) ? 1.f : 0.f;
    }
    for (int idx = tid; idx < 48 * 32; idx += TH) {
        int a = idx >> 5, r = idx & 31;
        float m = maskv[a];
        XB[a * PITCH + r] = SUBR[r * SUBP + a] * m * m;
    }
    if (tid >= 128 && tid < 256) {  // zero K-pad rows 356..359
        int rr = (tid - 128) & 31, row = 356 + ((tid - 128) >> 5);
        XA[row * PITCH + rr] = 0.f;
    }
    __syncthreads();

    // ---- stage A as GEMM: meanfeat = (X^T @ vf_b) * invs -> XA rows 100..355 ----
    mlp_gemm(XB, XA + 100 * PITCH, vf + b * 48 * 256, 0, invs, W0, W1, 48, 6, 2, tid);

    rownorm(XA + 100 * PITCH, red1, red2, rowM, rowR, tid);                // subset_weighted_norm
    mlp_gemm(XA, XB, cW, cB, 0, W0, W1, 356, 45, 0, tid);                  // combine + relu
    rownorm(XB, red1, red2, rowM, rowR, tid);                              // norm_post_combine
    mlp_gemm(XB, XA, w1, b1, 0, W0, W1, 256, 32, 0, tid);                  // l1 + relu
    mlp_gemm(XA, XB, w2a, b2a, 0, W0, W1, 256, 32, 1, tid);                // l2a + leaky
    mlp_gemm(XB, XA, w2b, b2b, 0, W0, W1, 256, 32, 0, tid);                // l2b: leaky+relu == relu
    rownorm(XA, red1, red2, rowM, rowR, tid);                              // norm_pre_score

    // ---- score head ----
    {
        int r = tid & 31, part = tid >> 5;
        float s = 0.f;
#pragma unroll
        for (int gg = 0; gg < 32; gg++)
            s += XA[(part * 32 + gg) * PITCH + r] * sW[part * 32 + gg];
        red1[part * 32 + r] = s;
        __syncthreads();
        if (tid < 32) {
            float t = 0.f;
#pragma unroll
            for (int p = 0; p < 8; p++) t += red1[p * 32 + tid];
            g_scores[b * 4096 + s0 + tid] = t + sB[0];
        }
    }
}

// ---------------- per-batch softmax over 4096 scores ----------------
__global__ void softmax_kernel(float* __restrict__ probs_out) {
    __shared__ float sbuf[32];
    __shared__ float sval;
    int b = blockIdx.x, t = threadIdx.x, lane = t & 31, wid = t >> 5;
    const float* sc = g_scores + b * 4096;
    float v0 = sc[t], v1 = sc[t + 1024], v2 = sc[t + 2048], v3 = sc[t + 3072];
    float mx = fmaxf(fmaxf(v0, v1), fmaxf(v2, v3));
#pragma unroll
    for (int o = 16; o; o >>= 1) mx = fmaxf(mx, __shfl_xor_sync(0xffffffffu, mx, o));
    if (lane == 0) sbuf[wid] = mx;
    __syncthreads();
    if (t < 32) {
        float m = sbuf[t];
#pragma unroll
        for (int o = 16; o; o >>= 1) m = fmaxf(m, __shfl_xor_sync(0xffffffffu, m, o));
        if (t == 0) sval = m;
    }
    __syncthreads();
    mx = sval;
    float e0 = expf(v0 - mx), e1 = expf(v1 - mx), e2 = expf(v2 - mx), e3 = expf(v3 - mx);
    float sum = e0 + e1 + e2 + e3;
#pragma unroll
    for (int o = 16; o; o >>= 1) sum += __shfl_xor_sync(0xffffffffu, sum, o);
    __syncthreads();
    if (lane == 0) sbuf[wid] = sum;
    __syncthreads();
    if (t < 32) {
        float s = sbuf[t];
#pragma unroll
        for (int o = 16; o; o >>= 1) s += __shfl_xor_sync(0xffffffffu, s, o);
        if (t == 0) sval = s;
    }
    __syncthreads();
    float inv = 1.f / sval;
    float p0 = e0 * inv, p1 = e1 * inv, p2 = e2 * inv, p3 = e3 * inv;
    probs_out[b * 4096 + t] = p0;
    probs_out[b * 4096 + t + 1024] = p1;
    probs_out[b * 4096 + t + 2048] = p2;
    probs_out[b * 4096 + t + 3072] = p3;
    g_probs[b * 4096 + t] = p0;
    g_probs[b * 4096 + t + 1024] = p1;
    g_probs[b * 4096 + t + 2048] = p2;
    g_probs[b * 4096 + t + 3072] = p3;
}

// ---------------- zero + scatter into spectral bins ----------------
__global__ void zero_kernel(float* __restrict__ p, int n) {
    int idx = blockIdx.x * blockDim.x + threadIdx.x;
    if (idx < n) p[idx] = 0.f;
}

__global__ void scatter_kernel(const int* __restrict__ midx,
                               const float* __restrict__ inten,
                               float* __restrict__ spect) {
    int idx = blockIdx.x * blockDim.x + threadIdx.x;
    if (idx >= 8 * 4096 * 32) return;
    int b = idx >> 17;              // 4096*32 = 131072
    int s = (idx >> 5) & 4095;
    float w = inten[idx] * g_probs[b * 4096 + s];
    atomicAdd(spect + b * 65536 + midx[idx], w);
}

// ---------------- launch ----------------
extern "C" void kernel_launch(void* const* d_in, const int* in_sizes, int n_in,
                              void* d_out, int out_size) {
    const float* vf    = (const float*)d_in[0];
    const float* vmask = (const float*)d_in[1];
    const float* eoh   = (const float*)d_in[2];
    const int*   subs  = (const int*)d_in[4];
    const int*   midx  = (const int*)d_in[6];
    const float* inten = (const float*)d_in[7];
    const float* cW    = (const float*)d_in[8];
    const float* cB    = (const float*)d_in[9];
    const float* w1    = (const float*)d_in[10];
    const float* b1    = (const float*)d_in[11];
    const float* w2a   = (const float*)d_in[12];
    const float* b2a   = (const float*)d_in[13];
    const float* w2b   = (const float*)d_in[14];
    const float* b2b   = (const float*)d_in[15];
    const float* sW    = (const float*)d_in[16];
    const float* sB    = (const float*)d_in[17];
    float* out = (float*)d_out;

    int pOff = out_size - 8 * 4096;  // spect first, probs second
    size_t smem = (size_t)27168 * sizeof(float);
    cudaFuncSetAttribute(fused_main, cudaFuncAttributeMaxDynamicSharedMemorySize,
                         (int)smem);

    zero_kernel<<<(pOff + 511) / 512, 512>>>(out, pOff);
    fused_main<<<1024, TH, smem>>>(vf, vmask, eoh, subs, cW, cB, w1, b1, w2a, b2a,
                                   w2b, b2b, sW, sB);
    softmax_kernel<<<8, 1024>>>(out + pOff);
    scatter_kernel<<<2048, 512>>>(midx, inten, out);
}